// round 8
// baseline (speedup 1.0000x reference)
#include <cuda_runtime.h>
#include <math.h>

#define NN 50000
#define NE 1600000
#define NF 256
#define NH 128
#define NC 40

// ---------------- scratch (no allocations allowed) ----------------
__device__ float g_dinv[NN];
__device__ int   g_cnt[NN];    // in-degree (excl. self-loop)
__device__ int   g_base[NN];   // CSR row start
__device__ int   g_cur[NN];    // fill cursor
__device__ int   g_eidx[NE];   // src node per edge, grouped by dst
__device__ float g_G1[(size_t)NN * NH];  // dinv * (X @ W1)
__device__ float g_H1[(size_t)NN * NH];  // relu(dinv*agg + b1) * mask
__device__ float g_G2[(size_t)NN * NC];  // dinv * (H1 @ W2)

// ---------------- CSR build ----------------
__global__ void k_zero() {
    int v = blockIdx.x * 256 + threadIdx.x;
    if (v < NN) g_cnt[v] = 0;
}

__global__ void k_hist(const int* __restrict__ dst) {
    int e = blockIdx.x * 256 + threadIdx.x;
    if (e < NE) atomicAdd(&g_cnt[dst[e]], 1);
}

// single block, 1024 threads: exclusive scan of g_cnt -> g_base/g_cur, plus dinv
__global__ __launch_bounds__(1024) void k_scan() {
    __shared__ int sums[1024];
    const int tid = threadIdx.x;
    const int CH = (NN + 1023) / 1024;           // 49
    const int start = tid * CH;
    const int end = min(start + CH, NN);
    int s = 0;
    for (int i = start; i < end; i++) s += g_cnt[i];
    sums[tid] = s;
    __syncthreads();
    for (int off = 1; off < 1024; off <<= 1) {
        int v = (tid >= off) ? sums[tid - off] : 0;
        __syncthreads();
        sums[tid] += v;
        __syncthreads();
    }
    int run = (tid == 0) ? 0 : sums[tid - 1];
    for (int i = start; i < end; i++) {
        int c = g_cnt[i];
        g_base[i] = run;
        g_cur[i]  = run;
        g_dinv[i] = rsqrtf((float)(c + 1));      // +1 self-loop
        run += c;
    }
}

__global__ void k_build(const int* __restrict__ src, const int* __restrict__ dst) {
    int e = blockIdx.x * 256 + threadIdx.x;
    if (e < NE) {
        int d = dst[e];
        int pos = atomicAdd(&g_cur[d], 1);
        g_eidx[pos] = src[e];
    }
}

// ---------------- GEMM1: G1 = dinv * (X @ W1) ----------------
// block: 256 threads, tile 128 rows x 128 cols, 8x8 per thread, K-step 8
__global__ __launch_bounds__(256) void k_gemm1(const float* __restrict__ x,
                                               const float* __restrict__ W1) {
    __shared__ float xs[128 * 8];   // [row][kk]
    __shared__ float ws[8 * 128];   // [kk][col]
    const int tid = threadIdx.x;
    const int txc = tid & 15;
    const int tyr = tid >> 4;
    const int row0 = blockIdx.x * 128;

    float acc[8][8];
#pragma unroll
    for (int r = 0; r < 8; r++)
#pragma unroll
        for (int c = 0; c < 8; c++) acc[r][c] = 0.f;

    const int xi = tid * 4;
    const int xrow = xi >> 3;
    const int xkk = xi & 7;
    const int gxr = min(row0 + xrow, NN - 1);
    const int wkk = tid >> 5;
    const int wcol = (tid & 31) * 4;

    for (int k0 = 0; k0 < NF; k0 += 8) {
        float4 xv = *(const float4*)&x[(size_t)gxr * NF + k0 + xkk];
        float4 wv = *(const float4*)&W1[(size_t)(k0 + wkk) * NH + wcol];
        __syncthreads();
        *(float4*)&xs[xrow * 8 + xkk] = xv;
        *(float4*)&ws[wkk * 128 + wcol] = wv;
        __syncthreads();
#pragma unroll
        for (int kk = 0; kk < 8; kk++) {
            float4 wa = *(float4*)&ws[kk * 128 + txc * 8];
            float4 wb = *(float4*)&ws[kk * 128 + txc * 8 + 4];
#pragma unroll
            for (int r = 0; r < 8; r++) {
                float xvv = xs[(tyr + 16 * r) * 8 + kk];
                acc[r][0] += xvv * wa.x; acc[r][1] += xvv * wa.y;
                acc[r][2] += xvv * wa.z; acc[r][3] += xvv * wa.w;
                acc[r][4] += xvv * wb.x; acc[r][5] += xvv * wb.y;
                acc[r][6] += xvv * wb.z; acc[r][7] += xvv * wb.w;
            }
        }
    }
#pragma unroll
    for (int r = 0; r < 8; r++) {
        int gr = row0 + tyr + 16 * r;
        if (gr < NN) {
            float dv = g_dinv[gr];
            float4 a, b;
            a.x = acc[r][0] * dv; a.y = acc[r][1] * dv;
            a.z = acc[r][2] * dv; a.w = acc[r][3] * dv;
            b.x = acc[r][4] * dv; b.y = acc[r][5] * dv;
            b.z = acc[r][6] * dv; b.w = acc[r][7] * dv;
            size_t off = (size_t)gr * NH + txc * 8;
            *(float4*)&g_G1[off] = a;
            *(float4*)&g_G1[off + 4] = b;
        }
    }
}

// ---------------- agg layer1 (CSR gather) + bias/relu/mask fused ----------------
// one block (128 threads) per node; thread = one feature column
__global__ __launch_bounds__(128) void k_agg1(const float* __restrict__ b1,
                                              const float* __restrict__ mask) {
    const int v = blockIdx.x;
    const int tid = threadIdx.x;
    float a0 = g_G1[(size_t)v * NH + tid];   // self-loop
    float a1 = 0.f, a2 = 0.f, a3 = 0.f;
    const int beg = g_base[v];
    const int n = g_cnt[v];
    int j = 0;
    for (; j + 4 <= n; j += 4) {
        int s0 = g_eidx[beg + j];
        int s1 = g_eidx[beg + j + 1];
        int s2 = g_eidx[beg + j + 2];
        int s3 = g_eidx[beg + j + 3];
        a0 += g_G1[(size_t)s0 * NH + tid];
        a1 += g_G1[(size_t)s1 * NH + tid];
        a2 += g_G1[(size_t)s2 * NH + tid];
        a3 += g_G1[(size_t)s3 * NH + tid];
    }
    for (; j < n; j++) {
        int s = g_eidx[beg + j];
        a0 += g_G1[(size_t)s * NH + tid];
    }
    float acc = (a0 + a1) + (a2 + a3);
    float h = fmaxf(fmaf(acc, g_dinv[v], b1[tid]), 0.f) * mask[(size_t)v * NH + tid];
    g_H1[(size_t)v * NH + tid] = h;
}

// ---------------- GEMM2: G2 = dinv * (H1 @ W2) ----------------
__global__ __launch_bounds__(320) void k_gemm2(const float* __restrict__ W2) {
    __shared__ float ws[NH * NC];  // 20 KB
    const int tid = threadIdx.x;
    for (int i = tid; i < NH * NC; i += 320) ws[i] = W2[i];
    __syncthreads();

    const int cg = tid % 10;
    const int rg = tid / 10;
    const int row0 = blockIdx.x * 128;

    float acc[4][4];
#pragma unroll
    for (int r = 0; r < 4; r++)
#pragma unroll
        for (int c = 0; c < 4; c++) acc[r][c] = 0.f;

    int grc[4];
#pragma unroll
    for (int r = 0; r < 4; r++) grc[r] = min(row0 + rg + 32 * r, NN - 1);

    for (int k0 = 0; k0 < NH; k0 += 4) {
        float4 hv[4];
#pragma unroll
        for (int r = 0; r < 4; r++)
            hv[r] = *(const float4*)&g_H1[(size_t)grc[r] * NH + k0];
#pragma unroll
        for (int kk = 0; kk < 4; kk++) {
            float4 w = *(float4*)&ws[(k0 + kk) * NC + cg * 4];
#pragma unroll
            for (int r = 0; r < 4; r++) {
                float xv = (kk == 0) ? hv[r].x : (kk == 1) ? hv[r].y
                         : (kk == 2) ? hv[r].z : hv[r].w;
                acc[r][0] += xv * w.x; acc[r][1] += xv * w.y;
                acc[r][2] += xv * w.z; acc[r][3] += xv * w.w;
            }
        }
    }
#pragma unroll
    for (int r = 0; r < 4; r++) {
        int gr = row0 + rg + 32 * r;
        if (gr < NN) {
            float dv = g_dinv[gr];
            float4 o;
            o.x = acc[r][0] * dv; o.y = acc[r][1] * dv;
            o.z = acc[r][2] * dv; o.w = acc[r][3] * dv;
            *(float4*)&g_G2[(size_t)gr * NC + cg * 4] = o;
        }
    }
}

// ---------------- agg layer2 (CSR gather) + bias + log_softmax fused ----------------
// one warp per node; lane handles col=lane and (if lane<8) col=32+lane
__global__ __launch_bounds__(256) void k_agg2(const float* __restrict__ b2,
                                              float* __restrict__ out) {
    const int w = (blockIdx.x * blockDim.x + threadIdx.x) >> 5;
    const int lane = threadIdx.x & 31;
    if (w >= NN) return;
    const size_t rb = (size_t)w * NC;
    const bool hi = (lane < NC - 32);

    float a0 = g_G2[rb + lane];                     // self-loop
    float a1 = hi ? g_G2[rb + 32 + lane] : 0.f;
    float c0 = 0.f, c1 = 0.f;
    const int beg = g_base[w];
    const int n = g_cnt[w];
    int j = 0;
    for (; j + 2 <= n; j += 2) {
        int s0 = g_eidx[beg + j];
        int s1 = g_eidx[beg + j + 1];
        size_t sb0 = (size_t)s0 * NC;
        size_t sb1 = (size_t)s1 * NC;
        a0 += g_G2[sb0 + lane];
        c0 += g_G2[sb1 + lane];
        if (hi) {
            a1 += g_G2[sb0 + 32 + lane];
            c1 += g_G2[sb1 + 32 + lane];
        }
    }
    if (j < n) {
        size_t sb = (size_t)g_eidx[beg + j] * NC;
        a0 += g_G2[sb + lane];
        if (hi) a1 += g_G2[sb + 32 + lane];
    }
    a0 += c0; a1 += c1;

    const float dv = g_dinv[w];
    float v0 = fmaf(a0, dv, b2[lane]);
    float v1 = hi ? fmaf(a1, dv, b2[32 + lane]) : -1e30f;

    float m = fmaxf(v0, v1);
#pragma unroll
    for (int o = 16; o; o >>= 1) m = fmaxf(m, __shfl_xor_sync(0xFFFFFFFFu, m, o));
    float s = expf(v0 - m) + (hi ? expf(v1 - m) : 0.f);
#pragma unroll
    for (int o = 16; o; o >>= 1) s += __shfl_xor_sync(0xFFFFFFFFu, s, o);
    float l = m + logf(s);
    out[rb + lane] = v0 - l;
    if (hi) out[rb + 32 + lane] = v1 - l;
}

// ---------------- launch ----------------
extern "C" void kernel_launch(void* const* d_in, const int* in_sizes, int n_in,
                              void* d_out, int out_size) {
    const float* x    = (const float*)d_in[0];
    const int*   ei   = (const int*)d_in[1];   // edge_index int32
    const float* W1   = (const float*)d_in[2];
    const float* b1   = (const float*)d_in[3];
    const float* W2   = (const float*)d_in[4];
    const float* b2   = (const float*)d_in[5];
    const float* mask = (const float*)d_in[6];
    float*       out  = (float*)d_out;

    const int* src = ei;
    const int* dst = ei + NE;

    k_zero  <<<(NN + 255) / 256, 256>>>();
    k_hist  <<<(NE + 255) / 256, 256>>>(dst);
    k_scan  <<<1, 1024>>>();
    k_build <<<(NE + 255) / 256, 256>>>(src, dst);

    k_gemm1 <<<(NN + 127) / 128, 256>>>(x, W1);
    k_agg1  <<<NN, 128>>>(b1, mask);

    k_gemm2 <<<(NN + 127) / 128, 320>>>(W2);
    k_agg2  <<<(NN * 32 + 255) / 256, 256>>>(b2, out);
}

// round 10
// speedup vs baseline: 1.1307x; 1.1307x over previous
#include <cuda_runtime.h>
#include <cuda_bf16.h>
#include <math.h>
#include <stdint.h>

#define NN 50000
#define NE 1600000
#define NF 256
#define NH 128
#define NC 40

// ---------------- scratch (no allocations allowed) ----------------
__device__ float g_dinv[NN];
__device__ int   g_cnt[NN];
__device__ int   g_base[NN];
__device__ int   g_cur[NN];
__device__ int   g_eidx[NE];
__device__ __align__(16) float g_G1[(size_t)NN * NH];
__device__ __align__(16) float g_H1[(size_t)NN * NH];
__device__ __align__(16) float g_G2[(size_t)NN * NC];
__device__ __align__(16) __nv_bfloat16 g_W1h[NF * NH];  // transposed: [n][k] = n*NF+k
__device__ __align__(16) __nv_bfloat16 g_W1l[NF * NH];

static __device__ __forceinline__ uint32_t pkbf(__nv_bfloat16 a, __nv_bfloat16 b) {
    uint16_t ua = *(uint16_t*)&a, ub = *(uint16_t*)&b;
    return (uint32_t)ua | ((uint32_t)ub << 16);
}

static __device__ __forceinline__ void hmma16816(float* c, uint32_t a0, uint32_t a1,
                                                 uint32_t a2, uint32_t a3,
                                                 uint32_t b0, uint32_t b1) {
    asm volatile("mma.sync.aligned.m16n8k16.row.col.f32.bf16.bf16.f32 "
                 "{%0,%1,%2,%3}, {%4,%5,%6,%7}, {%8,%9}, {%0,%1,%2,%3};"
                 : "+f"(c[0]), "+f"(c[1]), "+f"(c[2]), "+f"(c[3])
                 : "r"(a0), "r"(a1), "r"(a2), "r"(a3), "r"(b0), "r"(b1));
}

// ---------------- CSR build ----------------
__global__ void k_zero() {
    int v = blockIdx.x * 256 + threadIdx.x;
    if (v < NN) g_cnt[v] = 0;
}
__global__ void k_hist(const int* __restrict__ dst) {
    int e = blockIdx.x * 256 + threadIdx.x;
    if (e < NE) atomicAdd(&g_cnt[dst[e]], 1);
}
__global__ __launch_bounds__(1024) void k_scan() {
    __shared__ int sums[1024];
    const int tid = threadIdx.x;
    const int CH = (NN + 1023) / 1024;
    const int start = tid * CH;
    const int end = min(start + CH, NN);
    int s = 0;
    for (int i = start; i < end; i++) s += g_cnt[i];
    sums[tid] = s;
    __syncthreads();
    for (int off = 1; off < 1024; off <<= 1) {
        int v = (tid >= off) ? sums[tid - off] : 0;
        __syncthreads();
        sums[tid] += v;
        __syncthreads();
    }
    int run = (tid == 0) ? 0 : sums[tid - 1];
    for (int i = start; i < end; i++) {
        int c = g_cnt[i];
        g_base[i] = run;
        g_cur[i] = run;
        g_dinv[i] = rsqrtf((float)(c + 1));
        run += c;
    }
}
__global__ void k_build(const int* __restrict__ src, const int* __restrict__ dst) {
    int e = blockIdx.x * 256 + threadIdx.x;
    if (e < NE) {
        int pos = atomicAdd(&g_cur[dst[e]], 1);
        g_eidx[pos] = src[e];
    }
}

// ---------------- W1 prep: transpose + bf16 hi/lo split ----------------
__global__ void k_prepW(const float* __restrict__ W1) {
    int idx = blockIdx.x * 256 + threadIdx.x;
    if (idx >= NF * NH) return;
    int k = idx >> 7;
    int n = idx & 127;
    float v = W1[idx];                 // W1[k][n]
    __nv_bfloat16 h = __float2bfloat16(v);
    g_W1h[n * NF + k] = h;
    g_W1l[n * NF + k] = __float2bfloat16(v - __bfloat162float(h));
}

// ---------------- GEMM1 (mma.sync bf16, 3-term split): G1 = dinv * (X @ W1) ----------------
// 391 CTAs x 256 thr (8 warps). M-tile 128, N=128, K chunks of 32.
// smem word stride 20 per 32-bf16 row (conflict-free fragment loads, v4-alignable).
#define SSTR 20
__global__ __launch_bounds__(256) void k_gemm1_mma(const float* __restrict__ x) {
    __shared__ uint32_t uAh[128 * SSTR], uAl[128 * SSTR];
    __shared__ uint32_t uBh[128 * SSTR], uBl[128 * SSTR];

    const int tid = threadIdx.x;
    const int w = tid >> 5;          // warp 0..7 -> rows w*16..w*16+15
    const int lane = tid & 31;
    const int g = lane >> 2;         // group 0..7
    const int tig = lane & 3;        // thread-in-group
    const int row0 = blockIdx.x * 128;

    float acc[16][4];
#pragma unroll
    for (int nt = 0; nt < 16; nt++)
#pragma unroll
        for (int i = 0; i < 4; i++) acc[nt][i] = 0.f;

    for (int ch = 0; ch < 8; ch++) {
        const int k0 = ch * 32;
        __syncthreads();
        // ---- stage A: 128 rows x 32 k, fp32 -> bf16 hi/lo ----
#pragma unroll
        for (int q = 0; q < 4; q++) {
            int idx = tid + q * 256;          // (row, quad) : 128*8
            int ar = idx >> 3;
            int aq = idx & 7;
            int gr = min(row0 + ar, NN - 1);
            float4 v = *(const float4*)&x[(size_t)gr * NF + k0 + aq * 4];
            __nv_bfloat16 hx = __float2bfloat16(v.x), hy = __float2bfloat16(v.y);
            __nv_bfloat16 hz = __float2bfloat16(v.z), hw = __float2bfloat16(v.w);
            uint32_t* ph = &uAh[ar * SSTR + aq * 2];
            uint32_t* pl = &uAl[ar * SSTR + aq * 2];
            ph[0] = pkbf(hx, hy);
            ph[1] = pkbf(hz, hw);
            pl[0] = pkbf(__float2bfloat16(v.x - __bfloat162float(hx)),
                         __float2bfloat16(v.y - __bfloat162float(hy)));
            pl[1] = pkbf(__float2bfloat16(v.z - __bfloat162float(hz)),
                         __float2bfloat16(v.w - __bfloat162float(hw)));
        }
        // ---- stage B: 128 n x 32 k bf16, pre-split, uint4 copies ----
#pragma unroll
        for (int q = 0; q < 4; q++) {
            int idx = tid + q * 256;          // 1024 = 2 mats * 128 rows * 4 uint4
            int mat = idx >> 9;
            int br = (idx >> 2) & 127;
            int bc = idx & 3;
            const __nv_bfloat16* gsrc = mat ? g_W1l : g_W1h;
            uint4 v = *(const uint4*)&gsrc[(size_t)br * NF + k0 + bc * 8];
            uint32_t* p = (mat ? uBl : uBh) + br * SSTR + bc * 4;
            p[0] = v.x; p[1] = v.y; p[2] = v.z; p[3] = v.w;
        }
        __syncthreads();
        // ---- compute: 2 k-steps of 16 ----
#pragma unroll
        for (int ks = 0; ks < 2; ks++) {
            const int ko = ks * 8;
            const int ra0 = (w * 16 + g) * SSTR + tig + ko;
            const int ra1 = (w * 16 + g + 8) * SSTR + tig + ko;
            uint32_t ah0 = uAh[ra0],     ah1 = uAh[ra1];
            uint32_t ah2 = uAh[ra0 + 4], ah3 = uAh[ra1 + 4];
            uint32_t al0 = uAl[ra0],     al1 = uAl[ra1];
            uint32_t al2 = uAl[ra0 + 4], al3 = uAl[ra1 + 4];
#pragma unroll
            for (int nt = 0; nt < 16; nt++) {
                const int rb = (nt * 8 + g) * SSTR + tig + ko;
                uint32_t bh0 = uBh[rb], bh1 = uBh[rb + 4];
                uint32_t bl0 = uBl[rb], bl1 = uBl[rb + 4];
                hmma16816(acc[nt], ah0, ah1, ah2, ah3, bh0, bh1);
                hmma16816(acc[nt], ah0, ah1, ah2, ah3, bl0, bl1);
                hmma16816(acc[nt], al0, al1, al2, al3, bh0, bh1);
            }
        }
    }
    // ---- epilogue: scale by dinv, store ----
    const int r0 = row0 + w * 16 + g;
    const int r1 = r0 + 8;
    const float dv0 = (r0 < NN) ? g_dinv[r0] : 0.f;
    const float dv1 = (r1 < NN) ? g_dinv[r1] : 0.f;
#pragma unroll
    for (int nt = 0; nt < 16; nt++) {
        const int col = nt * 8 + tig * 2;
        if (r0 < NN) {
            float2 o0 = {acc[nt][0] * dv0, acc[nt][1] * dv0};
            *(float2*)&g_G1[(size_t)r0 * NH + col] = o0;
        }
        if (r1 < NN) {
            float2 o1 = {acc[nt][2] * dv1, acc[nt][3] * dv1};
            *(float2*)&g_G1[(size_t)r1 * NH + col] = o1;
        }
    }
}

// ---------------- agg layer1 (CSR gather) + bias/relu/mask fused ----------------
__global__ __launch_bounds__(128) void k_agg1(const float* __restrict__ b1,
                                              const float* __restrict__ mask) {
    const int v = blockIdx.x;
    const int tid = threadIdx.x;
    float a0 = g_G1[(size_t)v * NH + tid];
    float a1 = 0.f, a2 = 0.f, a3 = 0.f;
    const int beg = g_base[v];
    const int n = g_cnt[v];
    int j = 0;
    for (; j + 4 <= n; j += 4) {
        int s0 = g_eidx[beg + j];
        int s1 = g_eidx[beg + j + 1];
        int s2 = g_eidx[beg + j + 2];
        int s3 = g_eidx[beg + j + 3];
        a0 += g_G1[(size_t)s0 * NH + tid];
        a1 += g_G1[(size_t)s1 * NH + tid];
        a2 += g_G1[(size_t)s2 * NH + tid];
        a3 += g_G1[(size_t)s3 * NH + tid];
    }
    for (; j < n; j++) a0 += g_G1[(size_t)g_eidx[beg + j] * NH + tid];
    float acc = (a0 + a1) + (a2 + a3);
    float h = fmaxf(fmaf(acc, g_dinv[v], b1[tid]), 0.f) * mask[(size_t)v * NH + tid];
    g_H1[(size_t)v * NH + tid] = h;
}

// ---------------- GEMM2: G2 = dinv * (H1 @ W2) ----------------
__global__ __launch_bounds__(320) void k_gemm2(const float* __restrict__ W2) {
    __shared__ float ws[NH * NC];
    const int tid = threadIdx.x;
    for (int i = tid; i < NH * NC; i += 320) ws[i] = W2[i];
    __syncthreads();

    const int cg = tid % 10;
    const int rg = tid / 10;
    const int row0 = blockIdx.x * 128;

    float acc[4][4];
#pragma unroll
    for (int r = 0; r < 4; r++)
#pragma unroll
        for (int c = 0; c < 4; c++) acc[r][c] = 0.f;

    int grc[4];
#pragma unroll
    for (int r = 0; r < 4; r++) grc[r] = min(row0 + rg + 32 * r, NN - 1);

    for (int k0 = 0; k0 < NH; k0 += 4) {
        float4 hv[4];
#pragma unroll
        for (int r = 0; r < 4; r++)
            hv[r] = *(const float4*)&g_H1[(size_t)grc[r] * NH + k0];
#pragma unroll
        for (int kk = 0; kk < 4; kk++) {
            float4 wv = *(float4*)&ws[(k0 + kk) * NC + cg * 4];
#pragma unroll
            for (int r = 0; r < 4; r++) {
                float xv = (kk == 0) ? hv[r].x : (kk == 1) ? hv[r].y
                         : (kk == 2) ? hv[r].z : hv[r].w;
                acc[r][0] += xv * wv.x; acc[r][1] += xv * wv.y;
                acc[r][2] += xv * wv.z; acc[r][3] += xv * wv.w;
            }
        }
    }
#pragma unroll
    for (int r = 0; r < 4; r++) {
        int gr = row0 + rg + 32 * r;
        if (gr < NN) {
            float dv = g_dinv[gr];
            float4 o;
            o.x = acc[r][0] * dv; o.y = acc[r][1] * dv;
            o.z = acc[r][2] * dv; o.w = acc[r][3] * dv;
            *(float4*)&g_G2[(size_t)gr * NC + cg * 4] = o;
        }
    }
}

// ---------------- agg layer2 (CSR gather) + bias + log_softmax fused ----------------
__global__ __launch_bounds__(256) void k_agg2(const float* __restrict__ b2,
                                              float* __restrict__ out) {
    const int w = (blockIdx.x * blockDim.x + threadIdx.x) >> 5;
    const int lane = threadIdx.x & 31;
    if (w >= NN) return;
    const size_t rb = (size_t)w * NC;
    const bool hi = (lane < NC - 32);

    float a0 = g_G2[rb + lane];
    float a1 = hi ? g_G2[rb + 32 + lane] : 0.f;
    float c0 = 0.f, c1 = 0.f;
    const int beg = g_base[w];
    const int n = g_cnt[w];
    int j = 0;
    for (; j + 2 <= n; j += 2) {
        size_t sb0 = (size_t)g_eidx[beg + j] * NC;
        size_t sb1 = (size_t)g_eidx[beg + j + 1] * NC;
        a0 += g_G2[sb0 + lane];
        c0 += g_G2[sb1 + lane];
        if (hi) { a1 += g_G2[sb0 + 32 + lane]; c1 += g_G2[sb1 + 32 + lane]; }
    }
    if (j < n) {
        size_t sb = (size_t)g_eidx[beg + j] * NC;
        a0 += g_G2[sb + lane];
        if (hi) a1 += g_G2[sb + 32 + lane];
    }
    a0 += c0; a1 += c1;

    const float dv = g_dinv[w];
    float v0 = fmaf(a0, dv, b2[lane]);
    float v1 = hi ? fmaf(a1, dv, b2[32 + lane]) : -1e30f;

    float m = fmaxf(v0, v1);
#pragma unroll
    for (int o = 16; o; o >>= 1) m = fmaxf(m, __shfl_xor_sync(0xFFFFFFFFu, m, o));
    float s = expf(v0 - m) + (hi ? expf(v1 - m) : 0.f);
#pragma unroll
    for (int o = 16; o; o >>= 1) s += __shfl_xor_sync(0xFFFFFFFFu, s, o);
    float l = m + logf(s);
    out[rb + lane] = v0 - l;
    if (hi) out[rb + 32 + lane] = v1 - l;
}

// ---------------- launch ----------------
extern "C" void kernel_launch(void* const* d_in, const int* in_sizes, int n_in,
                              void* d_out, int out_size) {
    const float* x    = (const float*)d_in[0];
    const int*   ei   = (const int*)d_in[1];
    const float* W1   = (const float*)d_in[2];
    const float* b1   = (const float*)d_in[3];
    const float* W2   = (const float*)d_in[4];
    const float* b2   = (const float*)d_in[5];
    const float* mask = (const float*)d_in[6];
    float*       out  = (float*)d_out;

    const int* src = ei;
    const int* dst = ei + NE;

    k_zero  <<<(NN + 255) / 256, 256>>>();
    k_hist  <<<(NE + 255) / 256, 256>>>(dst);
    k_scan  <<<1, 1024>>>();
    k_build <<<(NE + 255) / 256, 256>>>(src, dst);

    k_prepW     <<<(NF * NH + 255) / 256, 256>>>(W1);
    k_gemm1_mma <<<(NN + 127) / 128, 256>>>(x);
    k_agg1      <<<NN, 128>>>(b1, mask);

    k_gemm2 <<<(NN + 127) / 128, 320>>>(W2);
    k_agg2  <<<(NN * 32 + 255) / 256, 256>>>(b2, out);
}